// round 4
// baseline (speedup 1.0000x reference)
#include <cuda_runtime.h>
#include <math_constants.h>

#define NROWS   131072
#define DDIM    64
#define KCODES  1024
#define KC      128
#define NCHUNK  8
#define STR     132          // padded smem row stride (floats) to break bank conflicts
#define SM_FLOATS (64*STR + 64*STR + KC + 128*STR)

__device__ __forceinline__ unsigned rotl32(unsigned x, int r) {
    return __funnelshift_l(x, x, r);
}

// threefry2x32 with fixed key (0, 42) — jax.random.key(42).
// Returns o0 ^ o1: the jax_threefry_partitionable (default since jax 0.4.36)
// random_bits value for 32-bit output with 64-bit counter (c0=hi, c1=lo).
__device__ __forceinline__ unsigned threefry_xor_0_42(unsigned c1) {
    const unsigned ks0 = 0u;
    const unsigned ks1 = 42u;
    const unsigned ks2 = 0x1BD11BDAu ^ ks0 ^ ks1;
    unsigned x0 = 0u + ks0;          // counter hi word is 0 (size < 2^32)
    unsigned x1 = c1 + ks1;
#define TFR(r) { x0 += x1; x1 = rotl32(x1, r); x1 ^= x0; }
    TFR(13) TFR(15) TFR(26) TFR(6)
    x0 += ks1; x1 += ks2 + 1u;
    TFR(17) TFR(29) TFR(16) TFR(24)
    x0 += ks2; x1 += ks0 + 2u;
    TFR(13) TFR(15) TFR(26) TFR(6)
    x0 += ks0; x1 += ks1 + 3u;
    TFR(17) TFR(29) TFR(16) TFR(24)
    x0 += ks1; x1 += ks2 + 4u;
    TFR(13) TFR(15) TFR(26) TFR(6)
    x0 += ks2; x1 += ks0 + 5u;
#undef TFR
    return x0 ^ x1;
}

// jax: u = max(tiny, (bits>>9) * 2^-23);  g = -log(-log(u))
// inner log via log1pf for u>=0.5 (u-1 exact) to keep winning-tail gumbels accurate.
__device__ __forceinline__ float gumbel_from_bits(unsigned bits) {
    float u = (float)(bits >> 9) * 1.1920928955078125e-7f;   // * 2^-23, exact
    u = fmaxf(u, 1.17549435e-38f);
    float v = (u < 0.5f) ? (-__logf(u)) : (-log1pf(u - 1.0f));
    return -__logf(v);
}

__global__ __launch_bounds__(256, 1)
void fused_quantize(const float* __restrict__ x,
                    const float* __restrict__ cbg,
                    const float* __restrict__ temp,
                    float* __restrict__ out,
                    int out_size)
{
    extern __shared__ float sm[];
    float* xs = sm;                    // [64 dims][128 rows] (stride STR)
    float* cb = sm + 64*STR;           // [64 dims][128 codes] (stride STR)
    float* cn = cb + 64*STR;           // [KC] ||c||^2 (reused as row softmax sum)
    float* es = cn + KC;               // [128 rows][KC] exp values (reused as reduction scratch)

    const int tid = threadIdx.x;
    const int tx  = tid & 15;          // phase A: code group of 8 / phase B: dim group
    const int ty  = tid >> 4;          // phase A: 4-row group    / phase B: 8-row group
    const int rbase = blockIdx.x * 128;

    const float invT = 1.0f / temp[0];

    // ---- load x tile transposed into smem (coalesced gmem reads) ----
    for (int i = tid; i < 128*64; i += 256) {
        int r = i >> 6;
        int d = i & 63;
        xs[d*STR + r] = x[(rbase + r)*DDIM + d];
    }

    // persistent per-thread state (lo = rows 0..63 of tile, hi = rows 64..127)
    float sum_lo[4], sum_hi[4], best_lo[4], best_hi[4];
    int   bi_lo[4],  bi_hi[4];
#pragma unroll
    for (int i = 0; i < 4; i++) {
        sum_lo[i] = 0.f; sum_hi[i] = 0.f;
        best_lo[i] = -CUDART_INF_F; best_hi[i] = -CUDART_INF_F;
        bi_lo[i] = 0; bi_hi[i] = 0;
    }
    float accB[8][4];
#pragma unroll
    for (int rr = 0; rr < 8; rr++)
#pragma unroll
        for (int dd = 0; dd < 4; dd++) accB[rr][dd] = 0.f;

    for (int c = 0; c < NCHUNK; c++) {
        const int kb = c * KC;
        __syncthreads();   // cb/es of previous chunk fully consumed (covers xs on c==0)

        // ---- load codebook chunk transposed ----
        for (int i = tid; i < KC*64; i += 256) {
            int j = i >> 6;
            int d = i & 63;
            cb[d*STR + j] = cbg[(kb + j)*DDIM + d];
        }
        __syncthreads();

        // ---- per-code squared norms ----
        if (tid < KC) {
            float s = 0.f;
#pragma unroll 8
            for (int d = 0; d < 64; d++) {
                float v = cb[d*STR + tid];
                s = fmaf(v, v, s);
            }
            cn[tid] = s;
        }
        __syncthreads();

        // ================= Phase A: dots + gumbel + exp =================
        float dlo[4][8], dhi[4][8];
#pragma unroll
        for (int i = 0; i < 4; i++)
#pragma unroll
            for (int j = 0; j < 8; j++) { dlo[i][j] = 0.f; dhi[i][j] = 0.f; }

#pragma unroll 4
        for (int d = 0; d < 64; d++) {
            const float* xrow = &xs[d*STR];
            float4 xl = *(const float4*)(xrow + ty*4);
            float4 xh = *(const float4*)(xrow + 64 + ty*4);
            const float* crow = &cb[d*STR + tx*8];
            float4 c0 = *(const float4*)(crow);
            float4 c1 = *(const float4*)(crow + 4);
            float xlv[4] = {xl.x, xl.y, xl.z, xl.w};
            float xhv[4] = {xh.x, xh.y, xh.z, xh.w};
            float cv[8]  = {c0.x, c0.y, c0.z, c0.w, c1.x, c1.y, c1.z, c1.w};
#pragma unroll
            for (int i = 0; i < 4; i++)
#pragma unroll
                for (int j = 0; j < 8; j++) {
                    dlo[i][j] = fmaf(xlv[i], cv[j], dlo[i][j]);
                    dhi[i][j] = fmaf(xhv[i], cv[j], dhi[i][j]);
                }
        }

#pragma unroll
        for (int i = 0; i < 4; i++) {
            const int rl = ty*4 + i;
            const unsigned grow = (unsigned)(rbase + rl);
            float e8lo[8], e8hi[8];
#pragma unroll
            for (int j = 0; j < 8; j++) {
                const int kl = tx*8 + j;
                const int kg = kb + kl;
                unsigned flat_lo = grow*1024u + (unsigned)kg;        // row rbase+rl
                unsigned flat_hi = flat_lo + 65536u;                 // row rbase+64+rl
                unsigned b0 = threefry_xor_0_42(flat_lo);
                unsigned b1 = threefry_xor_0_42(flat_hi);
                float cnk = cn[kl];
                float slo = fmaf(2.0f, dlo[i][j], -cnk);   // neg_dist + ||x||^2 (row const)
                float shi = fmaf(2.0f, dhi[i][j], -cnk);
                if (slo > best_lo[i]) { best_lo[i] = slo; bi_lo[i] = kg; }
                if (shi > best_hi[i]) { best_hi[i] = shi; bi_hi[i] = kg; }
                float el = __expf((slo + gumbel_from_bits(b0)) * invT);
                float eh = __expf((shi + gumbel_from_bits(b1)) * invT);
                sum_lo[i] += el; sum_hi[i] += eh;
                e8lo[j] = el; e8hi[j] = eh;
            }
            float* ep = &es[rl*STR + tx*8];
            *(float4*)(ep)     = make_float4(e8lo[0], e8lo[1], e8lo[2], e8lo[3]);
            *(float4*)(ep + 4) = make_float4(e8lo[4], e8lo[5], e8lo[6], e8lo[7]);
            float* ep2 = &es[(64 + rl)*STR + tx*8];
            *(float4*)(ep2)     = make_float4(e8hi[0], e8hi[1], e8hi[2], e8hi[3]);
            *(float4*)(ep2 + 4) = make_float4(e8hi[4], e8hi[5], e8hi[6], e8hi[7]);
        }
        __syncthreads();

        // ================= Phase B: acc += e * codebook =================
        // thread owns rows ty*8..ty*8+7, dims {tx, tx+16, tx+32, tx+48}
#pragma unroll 2
        for (int kv = 0; kv < KC; kv += 4) {
            float4 cv4[4];
#pragma unroll
            for (int dd = 0; dd < 4; dd++)
                cv4[dd] = *(const float4*)&cb[(tx + dd*16)*STR + kv];
#pragma unroll
            for (int rr = 0; rr < 8; rr++) {
                float4 ev = *(const float4*)&es[(ty*8 + rr)*STR + kv];
#pragma unroll
                for (int dd = 0; dd < 4; dd++) {
                    accB[rr][dd] = fmaf(ev.x, cv4[dd].x, accB[rr][dd]);
                    accB[rr][dd] = fmaf(ev.y, cv4[dd].y, accB[rr][dd]);
                    accB[rr][dd] = fmaf(ev.z, cv4[dd].z, accB[rr][dd]);
                    accB[rr][dd] = fmaf(ev.w, cv4[dd].w, accB[rr][dd]);
                }
            }
        }
    }
    __syncthreads();

    // ---- cross-thread reductions (scratch in es) ----
    float* sred  = es;                 // [16][128]
    float* bredf = es + 16*128;        // [16][128]
    int*   bredi = (int*)(es + 32*128);// [16][128]
#pragma unroll
    for (int i = 0; i < 4; i++) {
        int rl = ty*4 + i;
        sred [tx*128 + rl]      = sum_lo[i];
        sred [tx*128 + 64 + rl] = sum_hi[i];
        bredf[tx*128 + rl]      = best_lo[i];
        bredf[tx*128 + 64 + rl] = best_hi[i];
        bredi[tx*128 + rl]      = bi_lo[i];
        bredi[tx*128 + 64 + rl] = bi_hi[i];
    }
    __syncthreads();
    if (tid < 128) {
        int r = tid;
        float s = 0.f;
        float b = -CUDART_INF_F;
        int bi = 0;
#pragma unroll
        for (int t = 0; t < 16; t++) {
            s += sred[t*128 + r];
            float bv = bredf[t*128 + r];
            int   ii = bredi[t*128 + r];
            if (bv > b || (bv == b && ii < bi)) { b = bv; bi = ii; }
        }
        cn[r] = s;                     // row softmax denominator
        if (out_size >= NROWS*DDIM + NROWS)
            out[NROWS*DDIM + (rbase + r)] = (float)bi;    // ids (as f32)
    }
    __syncthreads();

    // ---- write emb = acc / sum ----
#pragma unroll
    for (int rr = 0; rr < 8; rr++) {
        int r = ty*8 + rr;
        float inv = 1.0f / cn[r];
#pragma unroll
        for (int dd = 0; dd < 4; dd++)
            out[(rbase + r)*DDIM + tx + dd*16] = accB[rr][dd] * inv;
    }
}

extern "C" void kernel_launch(void* const* d_in, const int* in_sizes, int n_in,
                              void* d_out, int out_size) {
    const float* x  = (const float*)d_in[0];
    const float* cb = (const float*)d_in[1];
    const float* t  = (const float*)d_in[2];
    float* out = (float*)d_out;

    size_t smem = SM_FLOATS * sizeof(float);   // 135680 B
    cudaFuncSetAttribute(fused_quantize,
                         cudaFuncAttributeMaxDynamicSharedMemorySize, (int)smem);
    fused_quantize<<<NROWS/128, 256, smem>>>(x, cb, t, out, out_size);
}

// round 5
// speedup vs baseline: 1.2987x; 1.2987x over previous
#include <cuda_runtime.h>
#include <math_constants.h>

#define NROWS   131072
#define DDIM    64
#define KCODES  1024
#define KC      128
#define NCHUNK  8
#define NTHR    512
#define STR     132          // padded smem row stride (floats); multiple of 4 for LDS.128
#define SM_FLOATS (64*STR + 64*STR + KC + 128*STR)

__device__ __forceinline__ unsigned rotl32(unsigned x, int r) {
    return __funnelshift_l(x, x, r);
}

// threefry2x32, key (0,42) — jax.random.key(42), partitionable path:
// bits[j] = o0 ^ o1 with counter (0, j).
__device__ __forceinline__ unsigned threefry_xor_0_42(unsigned c1) {
    const unsigned ks0 = 0u;
    const unsigned ks1 = 42u;
    const unsigned ks2 = 0x1BD11BDAu ^ ks0 ^ ks1;
    unsigned x0 = 0u + ks0;
    unsigned x1 = c1 + ks1;
#define TFR(r) { x0 += x1; x1 = rotl32(x1, r); x1 ^= x0; }
    TFR(13) TFR(15) TFR(26) TFR(6)
    x0 += ks1; x1 += ks2 + 1u;
    TFR(17) TFR(29) TFR(16) TFR(24)
    x0 += ks2; x1 += ks0 + 2u;
    TFR(13) TFR(15) TFR(26) TFR(6)
    x0 += ks0; x1 += ks1 + 3u;
    TFR(17) TFR(29) TFR(16) TFR(24)
    x0 += ks1; x1 += ks2 + 4u;
    TFR(13) TFR(15) TFR(26) TFR(6)
    x0 += ks2; x1 += ks0 + 5u;
#undef TFR
    return x0 ^ x1;
}

// jax: u = max(tiny, (bits>>9)*2^-23);  g = -log(-log(u))
__device__ __forceinline__ float gumbel_from_bits(unsigned bits) {
    float u = (float)(bits >> 9) * 1.1920928955078125e-7f;
    u = fmaxf(u, 1.17549435e-38f);
    float v = (u < 0.5f) ? (-__logf(u)) : (-log1pf(u - 1.0f));
    return -__logf(v);
}

__global__ __launch_bounds__(NTHR, 1)
void fused_quantize(const float* __restrict__ x,
                    const float* __restrict__ cbg,
                    const float* __restrict__ temp,
                    float* __restrict__ out,
                    int out_size)
{
    extern __shared__ float sm[];
    float* xs = sm;                    // [64 dims][128 rows]  stride STR
    float* cb = sm + 64*STR;           // [64 dims][128 codes] stride STR
    float* cn = cb + 64*STR;           // [KC] ||c||^2 (later: row softmax sums)
    float* es = cn + KC;               // [128 rows][KC] exp values (later: reduce scratch)

    const int tid = threadIdx.x;
    const int tx  = tid & 15;          // A: code-group of 8 / B: dim group
    const int ty  = tid >> 4;          // 0..31 : row group of 4
    const int rbase = blockIdx.x * 128;

    const float invT = 1.0f / temp[0];

    // ---- load x tile transposed (coalesced) ----
    for (int i = tid; i < 128*64; i += NTHR) {
        int r = i >> 6;
        int d = i & 63;
        xs[d*STR + r] = x[(rbase + r)*DDIM + d];
    }

    // persistent per-thread state: 4 rows (ty*4 .. ty*4+3)
    float sum4[4], best4[4];
    int   bi4[4];
#pragma unroll
    for (int i = 0; i < 4; i++) {
        sum4[i] = 0.f; best4[i] = -CUDART_INF_F; bi4[i] = 0;
    }
    float accB[4][4];
#pragma unroll
    for (int rr = 0; rr < 4; rr++)
#pragma unroll
        for (int dd = 0; dd < 4; dd++) accB[rr][dd] = 0.f;

    for (int c = 0; c < NCHUNK; c++) {
        const int kb = c * KC;
        __syncthreads();   // prev chunk's cb/es fully consumed (covers xs on c==0)

        // ---- load codebook chunk transposed ----
        for (int i = tid; i < KC*64; i += NTHR) {
            int j = i >> 6;
            int d = i & 63;
            cb[d*STR + j] = cbg[(kb + j)*DDIM + d];
        }
        __syncthreads();

        // ---- per-code squared norms ----
        if (tid < KC) {
            float s = 0.f;
#pragma unroll 8
            for (int d = 0; d < 64; d++) {
                float v = cb[d*STR + tid];
                s = fmaf(v, v, s);
            }
            cn[tid] = s;
        }
        __syncthreads();

        // ============ Phase A: dots (4 rows x 8 codes) + gumbel + exp ============
        float dt[4][8];
#pragma unroll
        for (int i = 0; i < 4; i++)
#pragma unroll
            for (int j = 0; j < 8; j++) dt[i][j] = 0.f;

#pragma unroll 8
        for (int d = 0; d < 64; d++) {
            const float* xrow = &xs[d*STR];
            float4 xv4 = *(const float4*)(xrow + ty*4);
            const float* crow = &cb[d*STR + tx*8];
            float4 c0 = *(const float4*)(crow);
            float4 c1 = *(const float4*)(crow + 4);
            float xv[4] = {xv4.x, xv4.y, xv4.z, xv4.w};
            float cv[8] = {c0.x, c0.y, c0.z, c0.w, c1.x, c1.y, c1.z, c1.w};
#pragma unroll
            for (int i = 0; i < 4; i++)
#pragma unroll
                for (int j = 0; j < 8; j++)
                    dt[i][j] = fmaf(xv[i], cv[j], dt[i][j]);
        }

#pragma unroll
        for (int i = 0; i < 4; i++) {
            const int rl = ty*4 + i;
            const unsigned base = (unsigned)(rbase + rl)*1024u + (unsigned)(kb + tx*8);
            float e8[8];
#pragma unroll
            for (int j = 0; j < 8; j++) {
                unsigned bits = threefry_xor_0_42(base + (unsigned)j);
                float s = fmaf(2.0f, dt[i][j], -cn[tx*8 + j]);  // neg_dist + ||x||^2
                if (s > best4[i]) { best4[i] = s; bi4[i] = kb + tx*8 + j; }
                float e = __expf((s + gumbel_from_bits(bits)) * invT);
                sum4[i] += e;
                e8[j] = e;
            }
            float* ep = &es[rl*STR + tx*8];
            *(float4*)(ep)     = make_float4(e8[0], e8[1], e8[2], e8[3]);
            *(float4*)(ep + 4) = make_float4(e8[4], e8[5], e8[6], e8[7]);
        }
        __syncthreads();

        // ============ Phase B: acc += e * codebook (4 rows x 4 dims) ============
        // thread owns rows ty*4..ty*4+3, dims {tx, tx+16, tx+32, tx+48}
#pragma unroll 4
        for (int kv = 0; kv < KC; kv += 4) {
            float4 cv4[4];
#pragma unroll
            for (int dd = 0; dd < 4; dd++)
                cv4[dd] = *(const float4*)&cb[(tx + dd*16)*STR + kv];
#pragma unroll
            for (int rr = 0; rr < 4; rr++) {
                float4 ev = *(const float4*)&es[(ty*4 + rr)*STR + kv];
#pragma unroll
                for (int dd = 0; dd < 4; dd++) {
                    accB[rr][dd] = fmaf(ev.x, cv4[dd].x, accB[rr][dd]);
                    accB[rr][dd] = fmaf(ev.y, cv4[dd].y, accB[rr][dd]);
                    accB[rr][dd] = fmaf(ev.z, cv4[dd].z, accB[rr][dd]);
                    accB[rr][dd] = fmaf(ev.w, cv4[dd].w, accB[rr][dd]);
                }
            }
        }
    }
    __syncthreads();

    // ---- cross-thread reductions over the 16 tx partials per row ----
    float* sred  = es;                  // [16][128]
    float* bredf = es + 16*128;         // [16][128]
    int*   bredi = (int*)(es + 32*128); // [16][128]
#pragma unroll
    for (int i = 0; i < 4; i++) {
        int rl = ty*4 + i;
        sred [tx*128 + rl] = sum4[i];
        bredf[tx*128 + rl] = best4[i];
        bredi[tx*128 + rl] = bi4[i];
    }
    __syncthreads();
    if (tid < 128) {
        int r = tid;
        float s = 0.f;
        float b = -CUDART_INF_F;
        int bi = 0;
#pragma unroll
        for (int t = 0; t < 16; t++) {
            s += sred[t*128 + r];
            float bv = bredf[t*128 + r];
            int   ii = bredi[t*128 + r];
            if (bv > b || (bv == b && ii < bi)) { b = bv; bi = ii; }
        }
        cn[r] = s;
        if (out_size >= NROWS*DDIM + NROWS)
            out[NROWS*DDIM + (rbase + r)] = (float)bi;
    }
    __syncthreads();

    // ---- write emb = acc / sum ----
#pragma unroll
    for (int rr = 0; rr < 4; rr++) {
        int r = ty*4 + rr;
        float inv = 1.0f / cn[r];
#pragma unroll
        for (int dd = 0; dd < 4; dd++)
            out[(rbase + r)*DDIM + tx + dd*16] = accB[rr][dd] * inv;
    }
}

extern "C" void kernel_launch(void* const* d_in, const int* in_sizes, int n_in,
                              void* d_out, int out_size) {
    const float* x  = (const float*)d_in[0];
    const float* cb = (const float*)d_in[1];
    const float* t  = (const float*)d_in[2];
    float* out = (float*)d_out;

    size_t smem = SM_FLOATS * sizeof(float);   // 135680 B
    cudaFuncSetAttribute(fused_quantize,
                         cudaFuncAttributeMaxDynamicSharedMemorySize, (int)smem);
    fused_quantize<<<NROWS/128, NTHR, smem>>>(x, cb, t, out, out_size);
}